// round 9
// baseline (speedup 1.0000x reference)
#include <cuda_runtime.h>
#include <cuda_fp16.h>
#include <cstdint>
#include <math.h>

// ---------------- problem dims ----------------
#define X_DIM 2048

// ---------------- scratch (static device mem; no allocs) ----------------
// All offsets in __half units. Each tensor has 3 fp16 planes (h, m, l*2^22).
#define ACTPL  8388608ull                  // activation plane [4096,2048]
#define ACT3   (3ull * ACTPL)
#define XB_OFF   176160768ull              // x: plane 4194304
#define WIN_OFF  188743680ull              // plane 2097152
#define WH0_OFF  195035136ull              // plane 4194304
#define WH1_OFF  207618048ull
#define WH2_OFF  220200960ull              // plane 8388608
#define WH3_OFF  245366784ull
#define WH4_OFF  257949696ull              // plane 8388608
#define WH5_OFF  283115520ull
#define WOUT_OFF 295698432ull              // plane 1048576
#define TOTAL_HALVES 298844160ull
__device__ __half g_h[TOTAL_HALVES];

#define LSCALE 4194304.0f                  // 2^22
#define LINV   (1.0f / 4194304.0f)

// ---------------- PTX helpers ----------------
__device__ __forceinline__ uint32_t smem_u32(const void* p) {
    uint32_t a;
    asm("{ .reg .u64 t; cvta.to.shared.u64 t, %1; cvt.u32.u64 %0, t; }" : "=r"(a) : "l"(p));
    return a;
}
#define CP_ASYNC16(dst, src) \
    asm volatile("cp.async.cg.shared.global [%0], [%1], 16;" :: "r"(dst), "l"(src) : "memory")
#define CP_COMMIT() asm volatile("cp.async.commit_group;" ::: "memory")
#define CP_WAIT(n)  asm volatile("cp.async.wait_group %0;" :: "n"(n) : "memory")

#define LDSM_X4(r0, r1, r2, r3, addr) \
    asm volatile("ldmatrix.sync.aligned.m8n8.x4.shared.b16 {%0,%1,%2,%3}, [%4];" \
                 : "=r"(r0), "=r"(r1), "=r"(r2), "=r"(r3) : "r"(addr))

// d += a*b (accumulate through TC)
#define MMA_F16(d, a0, a1, a2, a3, b0, b1) \
    asm volatile("mma.sync.aligned.m16n8k16.row.col.f32.f16.f16.f32 " \
                 "{%0,%1,%2,%3}, {%4,%5,%6,%7}, {%8,%9}, {%0,%1,%2,%3};" \
                 : "+f"((d)[0]), "+f"((d)[1]), "+f"((d)[2]), "+f"((d)[3]) \
                 : "r"(a0), "r"(a1), "r"(a2), "r"(a3), "r"(b0), "r"(b1))

// d = a*b (fresh zero accumulator — keeps TC RZ-accumulation chains short)
#define MMA_F16_Z(d, a0, a1, a2, a3, b0, b1) \
    asm volatile("mma.sync.aligned.m16n8k16.row.col.f32.f16.f16.f32 " \
                 "{%0,%1,%2,%3}, {%4,%5,%6,%7}, {%8,%9}, {%10,%11,%12,%13};" \
                 : "=f"((d)[0]), "=f"((d)[1]), "=f"((d)[2]), "=f"((d)[3]) \
                 : "r"(a0), "r"(a1), "r"(a2), "r"(a3), "r"(b0), "r"(b1), \
                   "f"(0.0f), "f"(0.0f), "f"(0.0f), "f"(0.0f))

__device__ __forceinline__ uint32_t swz(uint32_t off) { return off ^ ((off >> 3) & 0x70); }

__device__ __forceinline__ void split3(float v, __half& h, __half& m, __half& l) {
    h = __float2half_rn(v);
    float r1 = v - __half2float(h);
    m = __float2half_rn(r1);
    float r2 = r1 - __half2float(m);
    l = __float2half_rn(r2 * LSCALE);
}

// ---------------- prologue kernels ----------------
__global__ void split_copy3(const float* __restrict__ in, __half* __restrict__ o,
                            size_t plane, int n) {
    int i = blockIdx.x * blockDim.x + threadIdx.x;
    if (i < n) {
        __half h, m, l; split3(in[i], h, m, l);
        o[i] = h; o[i + plane] = m; o[i + 2 * plane] = l;
    }
}

// in [R,C] fp32 row-major -> out [C,R] fp16 row-major, 3 planes
__global__ void transpose_split3(const float* __restrict__ in, __half* __restrict__ o,
                                 size_t plane, int R, int C) {
    __shared__ float t[32][33];
    int cx = blockIdx.x * 32 + threadIdx.x;
    int r0 = blockIdx.y * 32;
#pragma unroll
    for (int j = threadIdx.y; j < 32; j += 8)
        t[j][threadIdx.x] = in[(size_t)(r0 + j) * C + cx];
    __syncthreads();
    int rx = r0 + threadIdx.x;
    int c0 = blockIdx.x * 32;
#pragma unroll
    for (int j = threadIdx.y; j < 32; j += 8) {
        __half h, m, l; split3(t[threadIdx.x][j], h, m, l);
        size_t idx = (size_t)(c0 + j) * R + rx;
        o[idx] = h; o[idx + plane] = m; o[idx + 2 * plane] = l;
    }
}

// ---------------- epilogue activation ----------------
__device__ __forceinline__ float epi(float v, float b, int a, float m) {
    v += b;
    float r;
    if (a == 0)      r = fmaxf(v, 0.0f);
    else if (a == 1) r = 1.0f / (1.0f + expf(-v));
    else if (a == 2) r = tanhf(v);
    else if (a == 3) r = (v >= 0.0f) ? v : 0.1f * v;
    else             r = (v > 0.0f) ? 1.0507009873554805f * v
                                    : 1.7580993408473766f * expm1f(v);
    return fminf(r, m);
}

// ---------------- fp16 3-split / 6-MMA GEMM, external fp32 accumulation ----------------
// C[4096, Ntot] = act( [A1 | A2] @ Wt^T + bias ).
// Operands: 3 fp16 planes (h, m, l*2^22) with given plane strides.
// Per k16 step the TC accumulator chain starts from ZERO and results are folded
// into register fp32 sums (RN) — avoids the tensor-core RZ accumulation bias.
#define STAGE_BYTES 98304           // 6 planes x 16KB
#define SM_TOTAL (2 * STAGE_BYTES)

__global__ __launch_bounds__(256, 1)
void gemm_f16x6(const __half* __restrict__ A1, size_t pA1,
                const __half* __restrict__ A2, size_t pA2,
                int lda1, int lda2, int K1, int Ktot,
                const __half* __restrict__ W, size_t pW, int ldw,
                const float* __restrict__ bias, const float* __restrict__ mo,
                const int* __restrict__ aid,
                void* __restrict__ Cout, size_t pC, int Ntot) {
    extern __shared__ char smem[];
    const uint32_t sb = smem_u32(smem);
    const int tid = threadIdx.x;
    const int block_m = blockIdx.y * 128;
    const int block_n = blockIdx.x * 128;

    // 8 warps as 2 (M) x 4 (N); warp tile 64x32
    const int warp = tid >> 5;
    const int lane = tid & 31;
    const int wm = warp >> 2;
    const int wn = warp & 3;
    const int g   = lane >> 2;
    const int tig = lane & 3;

    const int lrow = (lane & 7) + ((lane >> 3) & 1) * 8;
    const int lcol = ((lane >> 4) & 1) * 16;

    // loader geometry: row = tid>>1 (0..127), 4 consecutive 16B granules
    const int ldr_row = tid >> 1;
    const int ldr_q0  = (tid & 1) * 4;
    uint32_t dsto[4];
#pragma unroll
    for (int i = 0; i < 4; i++)
        dsto[i] = swz((uint32_t)(ldr_row * 128 + (ldr_q0 + i) * 16));

    const __half* a1p = A1 + (size_t)(block_m + ldr_row) * lda1 + ldr_q0 * 8;
    const __half* a2p = A2 + (size_t)(block_m + ldr_row) * lda2 + ldr_q0 * 8;
    const __half* bp  = W  + (size_t)(block_n + ldr_row) * ldw  + ldr_q0 * 8;

    float sumA[4][4][4], sumB[4][4][4];
#pragma unroll
    for (int i = 0; i < 4; i++)
#pragma unroll
        for (int j = 0; j < 4; j++)
#pragma unroll
            for (int c = 0; c < 4; c++) { sumA[i][j][c] = 0.0f; sumB[i][j][c] = 0.0f; }

    const int NC = Ktot / 64;

    auto load_stage = [&](int c, int s) {
        const uint32_t st = sb + s * STAGE_BYTES;
        const int k0 = c * 64;
        const __half* ap; size_t pa;
        if (k0 < K1) { ap = a1p + k0;        pa = pA1; }
        else         { ap = a2p + (k0 - K1); pa = pA2; }
#pragma unroll
        for (int p = 0; p < 3; p++) {
            const __half* src = ap + (size_t)p * pa;
#pragma unroll
            for (int i = 0; i < 4; i++) CP_ASYNC16(st + p * 16384 + dsto[i], src + i * 8);
        }
        const __half* wp = bp + k0;
#pragma unroll
        for (int p = 0; p < 3; p++) {
            const __half* src = wp + (size_t)p * pW;
#pragma unroll
            for (int i = 0; i < 4; i++) CP_ASYNC16(st + (3 + p) * 16384 + dsto[i], src + i * 8);
        }
        CP_COMMIT();
    };

    load_stage(0, 0);

    for (int c = 0; c < NC; c++) {
        const int b = c & 1;
        if (c + 1 < NC) { load_stage(c + 1, b ^ 1); CP_WAIT(1); }
        else            { CP_WAIT(0); }
        __syncthreads();

        const uint32_t Ahb = sb + b * STAGE_BYTES;
        const uint32_t Amb = Ahb + 16384;
        const uint32_t Alb = Ahb + 32768;
        const uint32_t Bhb = Ahb + 49152;
        const uint32_t Bmb = Ahb + 65536;
        const uint32_t Blb = Ahb + 81920;

#pragma unroll
        for (int k = 0; k < 4; k++) {       // 4 x k16 steps
            uint32_t bh[2][4], bm[2][4], bl[2][4];
#pragma unroll
            for (int nj = 0; nj < 2; nj++) {
                uint32_t off = swz((uint32_t)((wn * 32 + nj * 16 + lrow) * 128 + k * 32 + lcol));
                LDSM_X4(bh[nj][0], bh[nj][1], bh[nj][2], bh[nj][3], Bhb + off);
                LDSM_X4(bm[nj][0], bm[nj][1], bm[nj][2], bm[nj][3], Bmb + off);
                LDSM_X4(bl[nj][0], bl[nj][1], bl[nj][2], bl[nj][3], Blb + off);
            }
#pragma unroll
            for (int mi = 0; mi < 4; mi++) {
                uint32_t off = swz((uint32_t)((wm * 64 + mi * 16 + lrow) * 128 + k * 32 + lcol));
                uint32_t ah0, ah1, ah2, ah3, am0, am1, am2, am3, al0, al1, al2, al3;
                LDSM_X4(ah0, ah1, ah2, ah3, Ahb + off);
                LDSM_X4(am0, am1, am2, am3, Amb + off);
                LDSM_X4(al0, al1, al2, al3, Alb + off);
#pragma unroll
                for (int ni = 0; ni < 4; ni++) {
                    const int nj = ni >> 1, p = ni & 1;
                    float t[4], u[4];
                    // group A (native scales): hh + hm + mh + mm, fresh TC acc
                    MMA_F16_Z(t, ah0, ah1, ah2, ah3, bh[nj][p], bh[nj][p + 2]);
                    MMA_F16 (t, ah0, ah1, ah2, ah3, bm[nj][p], bm[nj][p + 2]);
                    MMA_F16 (t, am0, am1, am2, am3, bh[nj][p], bh[nj][p + 2]);
                    MMA_F16 (t, am0, am1, am2, am3, bm[nj][p], bm[nj][p + 2]);
                    sumA[mi][ni][0] += t[0]; sumA[mi][ni][1] += t[1];
                    sumA[mi][ni][2] += t[2]; sumA[mi][ni][3] += t[3];
                    // group B (scale 2^-22): h*l' + l'*h, fresh TC acc
                    MMA_F16_Z(u, ah0, ah1, ah2, ah3, bl[nj][p], bl[nj][p + 2]);
                    MMA_F16 (u, al0, al1, al2, al3, bh[nj][p], bh[nj][p + 2]);
                    sumB[mi][ni][0] += u[0]; sumB[mi][ni][1] += u[1];
                    sumB[mi][ni][2] += u[2]; sumB[mi][ni][3] += u[3];
                }
            }
        }
        __syncthreads();
    }

    // fused epilogue
    float bv[4][2], mv[4][2]; int av[4][2];
#pragma unroll
    for (int ni = 0; ni < 4; ni++) {
        int cc = block_n + wn * 32 + ni * 8 + 2 * tig;
        bv[ni][0] = bias[cc];     bv[ni][1] = bias[cc + 1];
        mv[ni][0] = mo[cc];       mv[ni][1] = mo[cc + 1];
        av[ni][0] = aid[cc];      av[ni][1] = aid[cc + 1];
    }
    if (pC != 0) {
        __half* Ch = (__half*)Cout;
#pragma unroll
        for (int mi = 0; mi < 4; mi++) {
            const int r0 = block_m + wm * 64 + mi * 16 + g;
#pragma unroll
            for (int ni = 0; ni < 4; ni++) {
                const int cc = block_n + wn * 32 + ni * 8 + 2 * tig;
#pragma unroll
                for (int hrow = 0; hrow < 2; hrow++) {
                    const size_t idx = (size_t)(r0 + hrow * 8) * Ntot + cc;
                    float v0 = epi(sumA[mi][ni][2*hrow+0] + sumB[mi][ni][2*hrow+0] * LINV,
                                   bv[ni][0], av[ni][0], mv[ni][0]);
                    float v1 = epi(sumA[mi][ni][2*hrow+1] + sumB[mi][ni][2*hrow+1] * LINV,
                                   bv[ni][1], av[ni][1], mv[ni][1]);
                    __half h0, m0, l0, h1, m1, l1;
                    split3(v0, h0, m0, l0);
                    split3(v1, h1, m1, l1);
                    *reinterpret_cast<__half2*>(Ch + idx)          = __halves2half2(h0, h1);
                    *reinterpret_cast<__half2*>(Ch + idx + pC)     = __halves2half2(m0, m1);
                    *reinterpret_cast<__half2*>(Ch + idx + 2 * pC) = __halves2half2(l0, l1);
                }
            }
        }
    } else {
        float* Cf = (float*)Cout;
#pragma unroll
        for (int mi = 0; mi < 4; mi++) {
            const int r0 = block_m + wm * 64 + mi * 16 + g;
#pragma unroll
            for (int ni = 0; ni < 4; ni++) {
                const int cc = block_n + wn * 32 + ni * 8 + 2 * tig;
#pragma unroll
                for (int hrow = 0; hrow < 2; hrow++) {
                    float2 v;
                    v.x = epi(sumA[mi][ni][2*hrow+0] + sumB[mi][ni][2*hrow+0] * LINV,
                              bv[ni][0], av[ni][0], mv[ni][0]);
                    v.y = epi(sumA[mi][ni][2*hrow+1] + sumB[mi][ni][2*hrow+1] * LINV,
                              bv[ni][1], av[ni][1], mv[ni][1]);
                    *reinterpret_cast<float2*>(Cf + (size_t)(r0 + hrow * 8) * Ntot + cc) = v;
                }
            }
        }
    }
}

// ---------------- host ----------------
extern "C" void kernel_launch(void* const* d_in, const int* in_sizes, int n_in,
                              void* d_out, int out_size) {
    const float* x     = (const float*)d_in[0];
    const float* W_in  = (const float*)d_in[1];
    const float* b_in  = (const float*)d_in[2];
    const float* Wh[6] = { (const float*)d_in[3], (const float*)d_in[4], (const float*)d_in[5],
                           (const float*)d_in[6], (const float*)d_in[7], (const float*)d_in[8] };
    const float* bh     = (const float*)d_in[9];
    const float* W_out  = (const float*)d_in[10];
    const float* b_out  = (const float*)d_in[11];
    const float* mo_in  = (const float*)d_in[12];
    const float* mo_h   = (const float*)d_in[13];
    const float* mo_out = (const float*)d_in[14];
    const int* aid_in   = (const int*)d_in[15];
    const int* aid_h    = (const int*)d_in[16];
    const int* aid_out  = (const int*)d_in[17];
    float* out = (float*)d_out;

    __half* s = nullptr;
    cudaGetSymbolAddress((void**)&s, g_h);

    cudaFuncSetAttribute(gemm_f16x6, cudaFuncAttributeMaxDynamicSharedMemorySize, SM_TOTAL);

    __half* O[7];
    for (int i = 0; i < 7; i++) O[i] = s + (size_t)i * ACT3;
    __half* XB   = s + XB_OFF;
    __half* WIN  = s + WIN_OFF;
    __half* WH0  = s + WH0_OFF;
    __half* WH1  = s + WH1_OFF;
    __half* WH2  = s + WH2_OFF;
    __half* WH3  = s + WH3_OFF;
    __half* WH4  = s + WH4_OFF;
    __half* WH5  = s + WH5_OFF;
    __half* WOUT = s + WOUT_OFF;

    dim3 tb(32, 8);
    split_copy3<<<16384, 256>>>(x, XB, 4194304ull, 4096 * 1024);
    transpose_split3<<<dim3(64, 32),  tb>>>(W_in,  WIN,  2097152ull, 1024, 2048);
    transpose_split3<<<dim3(64, 64),  tb>>>(Wh[0], WH0,  4194304ull, 2048, 2048);
    transpose_split3<<<dim3(64, 64),  tb>>>(Wh[1], WH1,  4194304ull, 2048, 2048);
    transpose_split3<<<dim3(64, 128), tb>>>(Wh[2], WH2,  8388608ull, 4096, 2048);
    transpose_split3<<<dim3(64, 64),  tb>>>(Wh[3], WH3,  4194304ull, 2048, 2048);
    transpose_split3<<<dim3(64, 128), tb>>>(Wh[4], WH4,  8388608ull, 4096, 2048);
    transpose_split3<<<dim3(64, 64),  tb>>>(Wh[5], WH5,  4194304ull, 2048, 2048);
    transpose_split3<<<dim3(16, 64),  tb>>>(W_out, WOUT, 1048576ull, 2048, 512);

    dim3 gX(16, 32), gO(4, 32);
    // input layer
    gemm_f16x6<<<gX, 256, SM_TOTAL>>>(XB, 4194304ull, XB, 4194304ull, 1024, 1024, 1024, 1024,
                                      WIN, 2097152ull, 1024,
                                      b_in, mo_in, aid_in, O[0], ACTPL, 2048);
    // hidden 0, 1
    gemm_f16x6<<<gX, 256, SM_TOTAL>>>(O[0], ACTPL, O[0], ACTPL, 2048, 2048, 2048, 2048,
                                      WH0, 4194304ull, 2048,
                                      bh + 0 * X_DIM, mo_h + 0 * X_DIM, aid_h + 0 * X_DIM,
                                      O[1], ACTPL, 2048);
    gemm_f16x6<<<gX, 256, SM_TOTAL>>>(O[1], ACTPL, O[1], ACTPL, 2048, 2048, 2048, 2048,
                                      WH1, 4194304ull, 2048,
                                      bh + 1 * X_DIM, mo_h + 1 * X_DIM, aid_h + 1 * X_DIM,
                                      O[2], ACTPL, 2048);
    // hidden 2: t = concat(outs[2], outs[1])
    gemm_f16x6<<<gX, 256, SM_TOTAL>>>(O[2], ACTPL, O[1], ACTPL, 2048, 2048, 2048, 4096,
                                      WH2, 8388608ull, 4096,
                                      bh + 2 * X_DIM, mo_h + 2 * X_DIM, aid_h + 2 * X_DIM,
                                      O[3], ACTPL, 2048);
    gemm_f16x6<<<gX, 256, SM_TOTAL>>>(O[3], ACTPL, O[3], ACTPL, 2048, 2048, 2048, 2048,
                                      WH3, 4194304ull, 2048,
                                      bh + 3 * X_DIM, mo_h + 3 * X_DIM, aid_h + 3 * X_DIM,
                                      O[4], ACTPL, 2048);
    // hidden 4: t = concat(outs[4], outs[3])
    gemm_f16x6<<<gX, 256, SM_TOTAL>>>(O[4], ACTPL, O[3], ACTPL, 2048, 2048, 2048, 4096,
                                      WH4, 8388608ull, 4096,
                                      bh + 4 * X_DIM, mo_h + 4 * X_DIM, aid_h + 4 * X_DIM,
                                      O[5], ACTPL, 2048);
    gemm_f16x6<<<gX, 256, SM_TOTAL>>>(O[5], ACTPL, O[5], ACTPL, 2048, 2048, 2048, 2048,
                                      WH5, 4194304ull, 2048,
                                      bh + 5 * X_DIM, mo_h + 5 * X_DIM, aid_h + 5 * X_DIM,
                                      O[6], ACTPL, 2048);
    // output layer -> fp32 d_out
    gemm_f16x6<<<gO, 256, SM_TOTAL>>>(O[6], ACTPL, O[6], ACTPL, 2048, 2048, 2048, 2048,
                                      WOUT, 1048576ull, 2048,
                                      b_out, mo_out, aid_out, out, 0ull, 512);
}

// round 10
// speedup vs baseline: 1.7968x; 1.7968x over previous
#include <cuda_runtime.h>
#include <cuda_fp16.h>
#include <cstdint>
#include <math.h>

// ---------------- problem dims ----------------
#define X_DIM 2048

// ---------------- scratch (static device mem; no allocs) ----------------
// All offsets in __half units. Each tensor has 2 fp16 planes (h, l = v - h).
#define ACTPL  8388608ull                  // activation plane [4096,2048]
#define ACT2   (2ull * ACTPL)
#define XB_OFF   117440512ull              // x: plane 4194304, 2 planes
#define WIN_OFF  125829120ull              // plane 2097152
#define WH0_OFF  130023424ull              // plane 4194304
#define WH1_OFF  138412032ull
#define WH2_OFF  146800640ull              // plane 8388608
#define WH3_OFF  163577856ull
#define WH4_OFF  171966464ull              // plane 8388608
#define WH5_OFF  188743680ull
#define WOUT_OFF 197132288ull              // plane 1048576
#define TOTAL_HALVES 199229440ull
__device__ __half g_h[TOTAL_HALVES];

// ---------------- PTX helpers ----------------
__device__ __forceinline__ uint32_t smem_u32(const void* p) {
    uint32_t a;
    asm("{ .reg .u64 t; cvta.to.shared.u64 t, %1; cvt.u32.u64 %0, t; }" : "=r"(a) : "l"(p));
    return a;
}
#define CP_ASYNC16(dst, src) \
    asm volatile("cp.async.cg.shared.global [%0], [%1], 16;" :: "r"(dst), "l"(src) : "memory")
#define CP_COMMIT() asm volatile("cp.async.commit_group;" ::: "memory")
#define CP_WAIT(n)  asm volatile("cp.async.wait_group %0;" :: "n"(n) : "memory")

#define LDSM_X4(r0, r1, r2, r3, addr) \
    asm volatile("ldmatrix.sync.aligned.m8n8.x4.shared.b16 {%0,%1,%2,%3}, [%4];" \
                 : "=r"(r0), "=r"(r1), "=r"(r2), "=r"(r3) : "r"(addr))

// d += a*b (accumulate through TC)
#define MMA_F16(d, a0, a1, a2, a3, b0, b1) \
    asm volatile("mma.sync.aligned.m16n8k16.row.col.f32.f16.f16.f32 " \
                 "{%0,%1,%2,%3}, {%4,%5,%6,%7}, {%8,%9}, {%0,%1,%2,%3};" \
                 : "+f"((d)[0]), "+f"((d)[1]), "+f"((d)[2]), "+f"((d)[3]) \
                 : "r"(a0), "r"(a1), "r"(a2), "r"(a3), "r"(b0), "r"(b1))

// d = a*b (fresh zero accumulator — keeps TC accumulation chains short)
#define MMA_F16_Z(d, a0, a1, a2, a3, b0, b1) \
    asm volatile("mma.sync.aligned.m16n8k16.row.col.f32.f16.f16.f32 " \
                 "{%0,%1,%2,%3}, {%4,%5,%6,%7}, {%8,%9}, {%10,%11,%12,%13};" \
                 : "=f"((d)[0]), "=f"((d)[1]), "=f"((d)[2]), "=f"((d)[3]) \
                 : "r"(a0), "r"(a1), "r"(a2), "r"(a3), "r"(b0), "r"(b1), \
                   "f"(0.0f), "f"(0.0f), "f"(0.0f), "f"(0.0f))

__device__ __forceinline__ uint32_t swz(uint32_t off) { return off ^ ((off >> 3) & 0x70); }

__device__ __forceinline__ void split2(float v, __half& h, __half& l) {
    h = __float2half_rn(v);
    l = __float2half_rn(v - __half2float(h));
}

// ---------------- prologue kernels ----------------
__global__ void split_copy2(const float* __restrict__ in, __half* __restrict__ o,
                            size_t plane, int n) {
    int i = blockIdx.x * blockDim.x + threadIdx.x;
    if (i < n) {
        __half h, l; split2(in[i], h, l);
        o[i] = h; o[i + plane] = l;
    }
}

// in [R,C] fp32 row-major -> out [C,R] fp16 row-major, 2 planes
__global__ void transpose_split2(const float* __restrict__ in, __half* __restrict__ o,
                                 size_t plane, int R, int C) {
    __shared__ float t[32][33];
    int cx = blockIdx.x * 32 + threadIdx.x;
    int r0 = blockIdx.y * 32;
#pragma unroll
    for (int j = threadIdx.y; j < 32; j += 8)
        t[j][threadIdx.x] = in[(size_t)(r0 + j) * C + cx];
    __syncthreads();
    int rx = r0 + threadIdx.x;
    int c0 = blockIdx.x * 32;
#pragma unroll
    for (int j = threadIdx.y; j < 32; j += 8) {
        __half h, l; split2(t[threadIdx.x][j], h, l);
        size_t idx = (size_t)(c0 + j) * R + rx;
        o[idx] = h; o[idx + plane] = l;
    }
}

// ---------------- epilogue activation ----------------
__device__ __forceinline__ float epi(float v, float b, int a, float m) {
    v += b;
    float r;
    if (a == 0)      r = fmaxf(v, 0.0f);
    else if (a == 1) r = 1.0f / (1.0f + expf(-v));
    else if (a == 2) r = tanhf(v);
    else if (a == 3) r = (v >= 0.0f) ? v : 0.1f * v;
    else             r = (v > 0.0f) ? 1.0507009873554805f * v
                                    : 1.7580993408473766f * expm1f(v);
    return fminf(r, m);
}

// ---------------- fp16 2-split / 3-MMA GEMM, external fp32 accumulation ----------------
// C[4096, Ntot] = act( [A1 | A2] @ Wt^T + bias ).
// Operands: 2 fp16 planes (h, l) with given plane strides.
// Per k16 step: t = ah*bh + ah*bl + al*bh in a short TC chain from zero,
// then folded into register fp32 sums (RN).
#define STAGE_BYTES 65536           // 4 planes x 16KB
#define NSTAGE 3
#define SM_TOTAL (NSTAGE * STAGE_BYTES)

__global__ __launch_bounds__(256, 1)
void gemm_f16x3(const __half* __restrict__ A1, size_t pA1,
                const __half* __restrict__ A2, size_t pA2,
                int lda1, int lda2, int K1, int Ktot,
                const __half* __restrict__ W, size_t pW, int ldw,
                const float* __restrict__ bias, const float* __restrict__ mo,
                const int* __restrict__ aid,
                void* __restrict__ Cout, size_t pC, int Ntot) {
    extern __shared__ char smem[];
    const uint32_t sb = smem_u32(smem);
    const int tid = threadIdx.x;
    const int block_m = blockIdx.y * 128;
    const int block_n = blockIdx.x * 128;

    // 8 warps as 2 (M) x 4 (N); warp tile 64x32
    const int warp = tid >> 5;
    const int lane = tid & 31;
    const int wm = warp >> 2;
    const int wn = warp & 3;
    const int g   = lane >> 2;
    const int tig = lane & 3;

    const int lrow = (lane & 7) + ((lane >> 3) & 1) * 8;
    const int lcol = ((lane >> 4) & 1) * 16;

    // loader geometry: row = tid>>1 (0..127), 4 consecutive 16B granules
    const int ldr_row = tid >> 1;
    const int ldr_q0  = (tid & 1) * 4;
    uint32_t dsto[4];
#pragma unroll
    for (int i = 0; i < 4; i++)
        dsto[i] = swz((uint32_t)(ldr_row * 128 + (ldr_q0 + i) * 16));

    const __half* a1p = A1 + (size_t)(block_m + ldr_row) * lda1 + ldr_q0 * 8;
    const __half* a2p = A2 + (size_t)(block_m + ldr_row) * lda2 + ldr_q0 * 8;
    const __half* bp  = W  + (size_t)(block_n + ldr_row) * ldw  + ldr_q0 * 8;

    float sum[4][4][4];
#pragma unroll
    for (int i = 0; i < 4; i++)
#pragma unroll
        for (int j = 0; j < 4; j++)
#pragma unroll
            for (int c = 0; c < 4; c++) sum[i][j][c] = 0.0f;

    const int NC = Ktot / 64;

    auto load_stage = [&](int c, int s) {
        const uint32_t st = sb + s * STAGE_BYTES;
        const int k0 = c * 64;
        const __half* ap; size_t pa;
        if (k0 < K1) { ap = a1p + k0;        pa = pA1; }
        else         { ap = a2p + (k0 - K1); pa = pA2; }
#pragma unroll
        for (int p = 0; p < 2; p++) {
            const __half* src = ap + (size_t)p * pa;
#pragma unroll
            for (int i = 0; i < 4; i++) CP_ASYNC16(st + p * 16384 + dsto[i], src + i * 8);
        }
        const __half* wp = bp + k0;
#pragma unroll
        for (int p = 0; p < 2; p++) {
            const __half* src = wp + (size_t)p * pW;
#pragma unroll
            for (int i = 0; i < 4; i++) CP_ASYNC16(st + (2 + p) * 16384 + dsto[i], src + i * 8);
        }
        CP_COMMIT();
    };

    load_stage(0, 0);
    load_stage(1, 1);

    for (int c = 0; c < NC; c++) {
        const int s = c % NSTAGE;
        if (c + 2 < NC) { load_stage(c + 2, (c + 2) % NSTAGE); CP_WAIT(2); }
        else if (c + 1 < NC) { CP_WAIT(1); }
        else { CP_WAIT(0); }
        __syncthreads();

        const uint32_t Ahb = sb + s * STAGE_BYTES;
        const uint32_t Alb = Ahb + 16384;
        const uint32_t Bhb = Ahb + 32768;
        const uint32_t Blb = Ahb + 49152;

#pragma unroll
        for (int k = 0; k < 4; k++) {       // 4 x k16 steps
            uint32_t bh[2][4], bl[2][4];
#pragma unroll
            for (int nj = 0; nj < 2; nj++) {
                uint32_t off = swz((uint32_t)((wn * 32 + nj * 16 + lrow) * 128 + k * 32 + lcol));
                LDSM_X4(bh[nj][0], bh[nj][1], bh[nj][2], bh[nj][3], Bhb + off);
                LDSM_X4(bl[nj][0], bl[nj][1], bl[nj][2], bl[nj][3], Blb + off);
            }
#pragma unroll
            for (int mi = 0; mi < 4; mi++) {
                uint32_t off = swz((uint32_t)((wm * 64 + mi * 16 + lrow) * 128 + k * 32 + lcol));
                uint32_t ah0, ah1, ah2, ah3, al0, al1, al2, al3;
                LDSM_X4(ah0, ah1, ah2, ah3, Ahb + off);
                LDSM_X4(al0, al1, al2, al3, Alb + off);
#pragma unroll
                for (int ni = 0; ni < 4; ni++) {
                    const int nj = ni >> 1, p = ni & 1;
                    float t[4];
                    // short TC chain from zero: hh + hl + lh
                    MMA_F16_Z(t, ah0, ah1, ah2, ah3, bh[nj][p], bh[nj][p + 2]);
                    MMA_F16 (t, ah0, ah1, ah2, ah3, bl[nj][p], bl[nj][p + 2]);
                    MMA_F16 (t, al0, al1, al2, al3, bh[nj][p], bh[nj][p + 2]);
                    sum[mi][ni][0] += t[0]; sum[mi][ni][1] += t[1];
                    sum[mi][ni][2] += t[2]; sum[mi][ni][3] += t[3];
                }
            }
        }
        __syncthreads();
    }

    // fused epilogue
    float bv[4][2], mv[4][2]; int av[4][2];
#pragma unroll
    for (int ni = 0; ni < 4; ni++) {
        int cc = block_n + wn * 32 + ni * 8 + 2 * tig;
        bv[ni][0] = bias[cc];     bv[ni][1] = bias[cc + 1];
        mv[ni][0] = mo[cc];       mv[ni][1] = mo[cc + 1];
        av[ni][0] = aid[cc];      av[ni][1] = aid[cc + 1];
    }
    if (pC != 0) {
        __half* Ch = (__half*)Cout;
#pragma unroll
        for (int mi = 0; mi < 4; mi++) {
            const int r0 = block_m + wm * 64 + mi * 16 + g;
#pragma unroll
            for (int ni = 0; ni < 4; ni++) {
                const int cc = block_n + wn * 32 + ni * 8 + 2 * tig;
#pragma unroll
                for (int hrow = 0; hrow < 2; hrow++) {
                    const size_t idx = (size_t)(r0 + hrow * 8) * Ntot + cc;
                    float v0 = epi(sum[mi][ni][2*hrow+0], bv[ni][0], av[ni][0], mv[ni][0]);
                    float v1 = epi(sum[mi][ni][2*hrow+1], bv[ni][1], av[ni][1], mv[ni][1]);
                    __half h0, l0, h1, l1;
                    split2(v0, h0, l0);
                    split2(v1, h1, l1);
                    *reinterpret_cast<__half2*>(Ch + idx)      = __halves2half2(h0, h1);
                    *reinterpret_cast<__half2*>(Ch + idx + pC) = __halves2half2(l0, l1);
                }
            }
        }
    } else {
        float* Cf = (float*)Cout;
#pragma unroll
        for (int mi = 0; mi < 4; mi++) {
            const int r0 = block_m + wm * 64 + mi * 16 + g;
#pragma unroll
            for (int ni = 0; ni < 4; ni++) {
                const int cc = block_n + wn * 32 + ni * 8 + 2 * tig;
#pragma unroll
                for (int hrow = 0; hrow < 2; hrow++) {
                    float2 v;
                    v.x = epi(sum[mi][ni][2*hrow+0], bv[ni][0], av[ni][0], mv[ni][0]);
                    v.y = epi(sum[mi][ni][2*hrow+1], bv[ni][1], av[ni][1], mv[ni][1]);
                    *reinterpret_cast<float2*>(Cf + (size_t)(r0 + hrow * 8) * Ntot + cc) = v;
                }
            }
        }
    }
}

// ---------------- host ----------------
extern "C" void kernel_launch(void* const* d_in, const int* in_sizes, int n_in,
                              void* d_out, int out_size) {
    const float* x     = (const float*)d_in[0];
    const float* W_in  = (const float*)d_in[1];
    const float* b_in  = (const float*)d_in[2];
    const float* Wh[6] = { (const float*)d_in[3], (const float*)d_in[4], (const float*)d_in[5],
                           (const float*)d_in[6], (const float*)d_in[7], (const float*)d_in[8] };
    const float* bh     = (const float*)d_in[9];
    const float* W_out  = (const float*)d_in[10];
    const float* b_out  = (const float*)d_in[11];
    const float* mo_in  = (const float*)d_in[12];
    const float* mo_h   = (const float*)d_in[13];
    const float* mo_out = (const float*)d_in[14];
    const int* aid_in   = (const int*)d_in[15];
    const int* aid_h    = (const int*)d_in[16];
    const int* aid_out  = (const int*)d_in[17];
    float* out = (float*)d_out;

    __half* s = nullptr;
    cudaGetSymbolAddress((void**)&s, g_h);

    cudaFuncSetAttribute(gemm_f16x3, cudaFuncAttributeMaxDynamicSharedMemorySize, SM_TOTAL);

    __half* O[7];
    for (int i = 0; i < 7; i++) O[i] = s + (size_t)i * ACT2;
    __half* XB   = s + XB_OFF;
    __half* WIN  = s + WIN_OFF;
    __half* WH0  = s + WH0_OFF;
    __half* WH1  = s + WH1_OFF;
    __half* WH2  = s + WH2_OFF;
    __half* WH3  = s + WH3_OFF;
    __half* WH4  = s + WH4_OFF;
    __half* WH5  = s + WH5_OFF;
    __half* WOUT = s + WOUT_OFF;

    dim3 tb(32, 8);
    split_copy2<<<16384, 256>>>(x, XB, 4194304ull, 4096 * 1024);
    transpose_split2<<<dim3(64, 32),  tb>>>(W_in,  WIN,  2097152ull, 1024, 2048);
    transpose_split2<<<dim3(64, 64),  tb>>>(Wh[0], WH0,  4194304ull, 2048, 2048);
    transpose_split2<<<dim3(64, 64),  tb>>>(Wh[1], WH1,  4194304ull, 2048, 2048);
    transpose_split2<<<dim3(64, 128), tb>>>(Wh[2], WH2,  8388608ull, 4096, 2048);
    transpose_split2<<<dim3(64, 64),  tb>>>(Wh[3], WH3,  4194304ull, 2048, 2048);
    transpose_split2<<<dim3(64, 128), tb>>>(Wh[4], WH4,  8388608ull, 4096, 2048);
    transpose_split2<<<dim3(64, 64),  tb>>>(Wh[5], WH5,  4194304ull, 2048, 2048);
    transpose_split2<<<dim3(16, 64),  tb>>>(W_out, WOUT, 1048576ull, 2048, 512);

    dim3 gX(16, 32), gO(4, 32);
    // input layer
    gemm_f16x3<<<gX, 256, SM_TOTAL>>>(XB, 4194304ull, XB, 4194304ull, 1024, 1024, 1024, 1024,
                                      WIN, 2097152ull, 1024,
                                      b_in, mo_in, aid_in, O[0], ACTPL, 2048);
    // hidden 0, 1
    gemm_f16x3<<<gX, 256, SM_TOTAL>>>(O[0], ACTPL, O[0], ACTPL, 2048, 2048, 2048, 2048,
                                      WH0, 4194304ull, 2048,
                                      bh + 0 * X_DIM, mo_h + 0 * X_DIM, aid_h + 0 * X_DIM,
                                      O[1], ACTPL, 2048);
    gemm_f16x3<<<gX, 256, SM_TOTAL>>>(O[1], ACTPL, O[1], ACTPL, 2048, 2048, 2048, 2048,
                                      WH1, 4194304ull, 2048,
                                      bh + 1 * X_DIM, mo_h + 1 * X_DIM, aid_h + 1 * X_DIM,
                                      O[2], ACTPL, 2048);
    // hidden 2: t = concat(outs[2], outs[1])
    gemm_f16x3<<<gX, 256, SM_TOTAL>>>(O[2], ACTPL, O[1], ACTPL, 2048, 2048, 2048, 4096,
                                      WH2, 8388608ull, 4096,
                                      bh + 2 * X_DIM, mo_h + 2 * X_DIM, aid_h + 2 * X_DIM,
                                      O[3], ACTPL, 2048);
    gemm_f16x3<<<gX, 256, SM_TOTAL>>>(O[3], ACTPL, O[3], ACTPL, 2048, 2048, 2048, 2048,
                                      WH3, 4194304ull, 2048,
                                      bh + 3 * X_DIM, mo_h + 3 * X_DIM, aid_h + 3 * X_DIM,
                                      O[4], ACTPL, 2048);
    // hidden 4: t = concat(outs[4], outs[3])
    gemm_f16x3<<<gX, 256, SM_TOTAL>>>(O[4], ACTPL, O[3], ACTPL, 2048, 2048, 2048, 4096,
                                      WH4, 8388608ull, 4096,
                                      bh + 4 * X_DIM, mo_h + 4 * X_DIM, aid_h + 4 * X_DIM,
                                      O[5], ACTPL, 2048);
    gemm_f16x3<<<gX, 256, SM_TOTAL>>>(O[5], ACTPL, O[5], ACTPL, 2048, 2048, 2048, 2048,
                                      WH5, 4194304ull, 2048,
                                      bh + 5 * X_DIM, mo_h + 5 * X_DIM, aid_h + 5 * X_DIM,
                                      O[6], ACTPL, 2048);
    // output layer -> fp32 d_out
    gemm_f16x3<<<gO, 256, SM_TOTAL>>>(O[6], ACTPL, O[6], ACTPL, 2048, 2048, 2048, 2048,
                                      WOUT, 1048576ull, 2048,
                                      b_out, mo_out, aid_out, out, 0ull, 512);
}

// round 11
// speedup vs baseline: 2.2728x; 1.2650x over previous
#include <cuda_runtime.h>
#include <cuda_fp16.h>
#include <cstdint>
#include <math.h>

// ---------------- problem dims ----------------
#define X_DIM 2048

// ---------------- scratch (static device mem; no allocs) ----------------
// All offsets in __half units. Each tensor has 2 fp16 planes (h, l = v - h).
#define ACTPL  8388608ull                  // activation plane [4096,2048]
#define ACT2   (2ull * ACTPL)
#define XB_OFF   117440512ull              // x: plane 4194304, 2 planes
#define WIN_OFF  125829120ull              // plane 2097152
#define WH0_OFF  130023424ull              // plane 4194304
#define WH1_OFF  138412032ull
#define WH2_OFF  146800640ull              // plane 8388608
#define WH3_OFF  163577856ull
#define WH4_OFF  171966464ull              // plane 8388608
#define WH5_OFF  188743680ull
#define WOUT_OFF 197132288ull              // plane 1048576
#define TOTAL_HALVES 199229440ull
__device__ __half g_h[TOTAL_HALVES];

// ---------------- PTX helpers ----------------
__device__ __forceinline__ uint32_t smem_u32(const void* p) {
    uint32_t a;
    asm("{ .reg .u64 t; cvta.to.shared.u64 t, %1; cvt.u32.u64 %0, t; }" : "=r"(a) : "l"(p));
    return a;
}
#define CP_ASYNC16(dst, src) \
    asm volatile("cp.async.cg.shared.global [%0], [%1], 16;" :: "r"(dst), "l"(src) : "memory")
#define CP_COMMIT() asm volatile("cp.async.commit_group;" ::: "memory")
#define CP_WAIT(n)  asm volatile("cp.async.wait_group %0;" :: "n"(n) : "memory")

#define LDSM_X4(r0, r1, r2, r3, addr) \
    asm volatile("ldmatrix.sync.aligned.m8n8.x4.shared.b16 {%0,%1,%2,%3}, [%4];" \
                 : "=r"(r0), "=r"(r1), "=r"(r2), "=r"(r3) : "r"(addr))

// d += a*b (accumulate through TC)
#define MMA_F16(d, a0, a1, a2, a3, b0, b1) \
    asm volatile("mma.sync.aligned.m16n8k16.row.col.f32.f16.f16.f32 " \
                 "{%0,%1,%2,%3}, {%4,%5,%6,%7}, {%8,%9}, {%0,%1,%2,%3};" \
                 : "+f"((d)[0]), "+f"((d)[1]), "+f"((d)[2]), "+f"((d)[3]) \
                 : "r"(a0), "r"(a1), "r"(a2), "r"(a3), "r"(b0), "r"(b1))

// d = a*b (fresh zero accumulator — keeps TC accumulation chains short)
#define MMA_F16_Z(d, a0, a1, a2, a3, b0, b1) \
    asm volatile("mma.sync.aligned.m16n8k16.row.col.f32.f16.f16.f32 " \
                 "{%0,%1,%2,%3}, {%4,%5,%6,%7}, {%8,%9}, {%10,%11,%12,%13};" \
                 : "=f"((d)[0]), "=f"((d)[1]), "=f"((d)[2]), "=f"((d)[3]) \
                 : "r"(a0), "r"(a1), "r"(a2), "r"(a3), "r"(b0), "r"(b1), \
                   "f"(0.0f), "f"(0.0f), "f"(0.0f), "f"(0.0f))

__device__ __forceinline__ uint32_t swz(uint32_t off) { return off ^ ((off >> 3) & 0x70); }

__device__ __forceinline__ void split2(float v, __half& h, __half& l) {
    h = __float2half_rn(v);
    l = __float2half_rn(v - __half2float(h));
}

// ---------------- prologue kernels ----------------
__global__ void split_copy2(const float* __restrict__ in, __half* __restrict__ o,
                            size_t plane, int n) {
    int i = blockIdx.x * blockDim.x + threadIdx.x;
    if (i < n) {
        __half h, l; split2(in[i], h, l);
        o[i] = h; o[i + plane] = l;
    }
}

// in [R,C] fp32 row-major -> out [C,R] fp16 row-major, 2 planes
__global__ void transpose_split2(const float* __restrict__ in, __half* __restrict__ o,
                                 size_t plane, int R, int C) {
    __shared__ float t[32][33];
    int cx = blockIdx.x * 32 + threadIdx.x;
    int r0 = blockIdx.y * 32;
#pragma unroll
    for (int j = threadIdx.y; j < 32; j += 8)
        t[j][threadIdx.x] = in[(size_t)(r0 + j) * C + cx];
    __syncthreads();
    int rx = r0 + threadIdx.x;
    int c0 = blockIdx.x * 32;
#pragma unroll
    for (int j = threadIdx.y; j < 32; j += 8) {
        __half h, l; split2(t[threadIdx.x][j], h, l);
        size_t idx = (size_t)(c0 + j) * R + rx;
        o[idx] = h; o[idx + plane] = l;
    }
}

// ---------------- epilogue activation ----------------
__device__ __forceinline__ float epi(float v, float b, int a, float m) {
    v += b;
    float r;
    if (a == 0)      r = fmaxf(v, 0.0f);
    else if (a == 1) r = 1.0f / (1.0f + expf(-v));
    else if (a == 2) r = tanhf(v);
    else if (a == 3) r = (v >= 0.0f) ? v : 0.1f * v;
    else             r = (v > 0.0f) ? 1.0507009873554805f * v
                                    : 1.7580993408473766f * expm1f(v);
    return fminf(r, m);
}

// ---------------- fp16 2-split / 3-MMA GEMM, external fp32 accumulation ----------------
// C[4096, Ntot] = act( [A1 | A2] @ Wt^T + bias ).
// 512 threads, 16 warps as 4(M) x 4(N); warp tile 32x32 on a 128x128x64 CTA tile.
// Per k16 step: t = ah*bh + ah*bl + al*bh in a short TC chain from zero,
// then folded into register fp32 sums (RN).
#define STAGE_BYTES 65536           // 4 planes x 16KB
#define NSTAGE 3
#define SM_TOTAL (NSTAGE * STAGE_BYTES)

__global__ __launch_bounds__(512, 1)
void gemm_f16x3(const __half* __restrict__ A1, size_t pA1,
                const __half* __restrict__ A2, size_t pA2,
                int lda1, int lda2, int K1, int Ktot,
                const __half* __restrict__ W, size_t pW, int ldw,
                const float* __restrict__ bias, const float* __restrict__ mo,
                const int* __restrict__ aid,
                void* __restrict__ Cout, size_t pC, int Ntot) {
    extern __shared__ char smem[];
    const uint32_t sb = smem_u32(smem);
    const int tid = threadIdx.x;
    const int block_m = blockIdx.y * 128;
    const int block_n = blockIdx.x * 128;

    // 16 warps as 4 (M) x 4 (N); warp tile 32x32
    const int warp = tid >> 5;
    const int lane = tid & 31;
    const int wm = warp >> 2;           // 0..3 -> m offset wm*32
    const int wn = warp & 3;            // 0..3 -> n offset wn*32
    const int g   = lane >> 2;
    const int tig = lane & 3;

    const int lrow = (lane & 7) + ((lane >> 3) & 1) * 8;
    const int lcol = ((lane >> 4) & 1) * 16;

    // loader geometry: 512 threads; row = tid>>2 (0..127), 2 consecutive 16B granules
    const int ldr_row = tid >> 2;
    const int ldr_q0  = (tid & 3) * 2;      // granule index 0,2,4,6
    uint32_t dsto[2];
#pragma unroll
    for (int i = 0; i < 2; i++)
        dsto[i] = swz((uint32_t)(ldr_row * 128 + (ldr_q0 + i) * 16));

    const __half* a1p = A1 + (size_t)(block_m + ldr_row) * lda1 + ldr_q0 * 8;
    const __half* a2p = A2 + (size_t)(block_m + ldr_row) * lda2 + ldr_q0 * 8;
    const __half* bp  = W  + (size_t)(block_n + ldr_row) * ldw  + ldr_q0 * 8;

    float sum[2][4][4];
#pragma unroll
    for (int i = 0; i < 2; i++)
#pragma unroll
        for (int j = 0; j < 4; j++)
#pragma unroll
            for (int c = 0; c < 4; c++) sum[i][j][c] = 0.0f;

    const int NC = Ktot / 64;

    auto load_stage = [&](int c, int s) {
        const uint32_t st = sb + s * STAGE_BYTES;
        const int k0 = c * 64;
        const __half* ap; size_t pa;
        if (k0 < K1) { ap = a1p + k0;        pa = pA1; }
        else         { ap = a2p + (k0 - K1); pa = pA2; }
#pragma unroll
        for (int p = 0; p < 2; p++) {
            const __half* src = ap + (size_t)p * pa;
#pragma unroll
            for (int i = 0; i < 2; i++) CP_ASYNC16(st + p * 16384 + dsto[i], src + i * 8);
        }
        const __half* wp = bp + k0;
#pragma unroll
        for (int p = 0; p < 2; p++) {
            const __half* src = wp + (size_t)p * pW;
#pragma unroll
            for (int i = 0; i < 2; i++) CP_ASYNC16(st + (2 + p) * 16384 + dsto[i], src + i * 8);
        }
        CP_COMMIT();
    };

    load_stage(0, 0);
    load_stage(1, 1);

    for (int c = 0; c < NC; c++) {
        const int s = c % NSTAGE;
        if (c + 2 < NC) { load_stage(c + 2, (c + 2) % NSTAGE); CP_WAIT(2); }
        else if (c + 1 < NC) { CP_WAIT(1); }
        else { CP_WAIT(0); }
        __syncthreads();

        const uint32_t Ahb = sb + s * STAGE_BYTES;
        const uint32_t Alb = Ahb + 16384;
        const uint32_t Bhb = Ahb + 32768;
        const uint32_t Blb = Ahb + 49152;

#pragma unroll
        for (int k = 0; k < 4; k++) {       // 4 x k16 steps
            uint32_t bh[2][4], bl[2][4];
#pragma unroll
            for (int nj = 0; nj < 2; nj++) {
                uint32_t off = swz((uint32_t)((wn * 32 + nj * 16 + lrow) * 128 + k * 32 + lcol));
                LDSM_X4(bh[nj][0], bh[nj][1], bh[nj][2], bh[nj][3], Bhb + off);
                LDSM_X4(bl[nj][0], bl[nj][1], bl[nj][2], bl[nj][3], Blb + off);
            }
#pragma unroll
            for (int mi = 0; mi < 2; mi++) {
                uint32_t off = swz((uint32_t)((wm * 32 + mi * 16 + lrow) * 128 + k * 32 + lcol));
                uint32_t ah0, ah1, ah2, ah3, al0, al1, al2, al3;
                LDSM_X4(ah0, ah1, ah2, ah3, Ahb + off);
                LDSM_X4(al0, al1, al2, al3, Alb + off);
#pragma unroll
                for (int ni = 0; ni < 4; ni++) {
                    const int nj = ni >> 1, p = ni & 1;
                    float t[4];
                    // short TC chain from zero: hh + hl + lh
                    MMA_F16_Z(t, ah0, ah1, ah2, ah3, bh[nj][p], bh[nj][p + 2]);
                    MMA_F16 (t, ah0, ah1, ah2, ah3, bl[nj][p], bl[nj][p + 2]);
                    MMA_F16 (t, al0, al1, al2, al3, bh[nj][p], bh[nj][p + 2]);
                    sum[mi][ni][0] += t[0]; sum[mi][ni][1] += t[1];
                    sum[mi][ni][2] += t[2]; sum[mi][ni][3] += t[3];
                }
            }
        }
        __syncthreads();
    }

    // fused epilogue
    float bv[4][2], mv[4][2]; int av[4][2];
#pragma unroll
    for (int ni = 0; ni < 4; ni++) {
        int cc = block_n + wn * 32 + ni * 8 + 2 * tig;
        bv[ni][0] = bias[cc];     bv[ni][1] = bias[cc + 1];
        mv[ni][0] = mo[cc];       mv[ni][1] = mo[cc + 1];
        av[ni][0] = aid[cc];      av[ni][1] = aid[cc + 1];
    }
    if (pC != 0) {
        __half* Ch = (__half*)Cout;
#pragma unroll
        for (int mi = 0; mi < 2; mi++) {
            const int r0 = block_m + wm * 32 + mi * 16 + g;
#pragma unroll
            for (int ni = 0; ni < 4; ni++) {
                const int cc = block_n + wn * 32 + ni * 8 + 2 * tig;
#pragma unroll
                for (int hrow = 0; hrow < 2; hrow++) {
                    const size_t idx = (size_t)(r0 + hrow * 8) * Ntot + cc;
                    float v0 = epi(sum[mi][ni][2*hrow+0], bv[ni][0], av[ni][0], mv[ni][0]);
                    float v1 = epi(sum[mi][ni][2*hrow+1], bv[ni][1], av[ni][1], mv[ni][1]);
                    __half h0, l0, h1, l1;
                    split2(v0, h0, l0);
                    split2(v1, h1, l1);
                    *reinterpret_cast<__half2*>(Ch + idx)      = __halves2half2(h0, h1);
                    *reinterpret_cast<__half2*>(Ch + idx + pC) = __halves2half2(l0, l1);
                }
            }
        }
    } else {
        float* Cf = (float*)Cout;
#pragma unroll
        for (int mi = 0; mi < 2; mi++) {
            const int r0 = block_m + wm * 32 + mi * 16 + g;
#pragma unroll
            for (int ni = 0; ni < 4; ni++) {
                const int cc = block_n + wn * 32 + ni * 8 + 2 * tig;
#pragma unroll
                for (int hrow = 0; hrow < 2; hrow++) {
                    float2 v;
                    v.x = epi(sum[mi][ni][2*hrow+0], bv[ni][0], av[ni][0], mv[ni][0]);
                    v.y = epi(sum[mi][ni][2*hrow+1], bv[ni][1], av[ni][1], mv[ni][1]);
                    *reinterpret_cast<float2*>(Cf + (size_t)(r0 + hrow * 8) * Ntot + cc) = v;
                }
            }
        }
    }
}

// ---------------- host ----------------
extern "C" void kernel_launch(void* const* d_in, const int* in_sizes, int n_in,
                              void* d_out, int out_size) {
    const float* x     = (const float*)d_in[0];
    const float* W_in  = (const float*)d_in[1];
    const float* b_in  = (const float*)d_in[2];
    const float* Wh[6] = { (const float*)d_in[3], (const float*)d_in[4], (const float*)d_in[5],
                           (const float*)d_in[6], (const float*)d_in[7], (const float*)d_in[8] };
    const float* bh     = (const float*)d_in[9];
    const float* W_out  = (const float*)d_in[10];
    const float* b_out  = (const float*)d_in[11];
    const float* mo_in  = (const float*)d_in[12];
    const float* mo_h   = (const float*)d_in[13];
    const float* mo_out = (const float*)d_in[14];
    const int* aid_in   = (const int*)d_in[15];
    const int* aid_h    = (const int*)d_in[16];
    const int* aid_out  = (const int*)d_in[17];
    float* out = (float*)d_out;

    __half* s = nullptr;
    cudaGetSymbolAddress((void**)&s, g_h);

    cudaFuncSetAttribute(gemm_f16x3, cudaFuncAttributeMaxDynamicSharedMemorySize, SM_TOTAL);

    __half* O[7];
    for (int i = 0; i < 7; i++) O[i] = s + (size_t)i * ACT2;
    __half* XB   = s + XB_OFF;
    __half* WIN  = s + WIN_OFF;
    __half* WH0  = s + WH0_OFF;
    __half* WH1  = s + WH1_OFF;
    __half* WH2  = s + WH2_OFF;
    __half* WH3  = s + WH3_OFF;
    __half* WH4  = s + WH4_OFF;
    __half* WH5  = s + WH5_OFF;
    __half* WOUT = s + WOUT_OFF;

    dim3 tb(32, 8);
    split_copy2<<<16384, 256>>>(x, XB, 4194304ull, 4096 * 1024);
    transpose_split2<<<dim3(64, 32),  tb>>>(W_in,  WIN,  2097152ull, 1024, 2048);
    transpose_split2<<<dim3(64, 64),  tb>>>(Wh[0], WH0,  4194304ull, 2048, 2048);
    transpose_split2<<<dim3(64, 64),  tb>>>(Wh[1], WH1,  4194304ull, 2048, 2048);
    transpose_split2<<<dim3(64, 128), tb>>>(Wh[2], WH2,  8388608ull, 4096, 2048);
    transpose_split2<<<dim3(64, 64),  tb>>>(Wh[3], WH3,  4194304ull, 2048, 2048);
    transpose_split2<<<dim3(64, 128), tb>>>(Wh[4], WH4,  8388608ull, 4096, 2048);
    transpose_split2<<<dim3(64, 64),  tb>>>(Wh[5], WH5,  4194304ull, 2048, 2048);
    transpose_split2<<<dim3(16, 64),  tb>>>(W_out, WOUT, 1048576ull, 2048, 512);

    dim3 gX(16, 32), gO(4, 32);
    // input layer
    gemm_f16x3<<<gX, 512, SM_TOTAL>>>(XB, 4194304ull, XB, 4194304ull, 1024, 1024, 1024, 1024,
                                      WIN, 2097152ull, 1024,
                                      b_in, mo_in, aid_in, O[0], ACTPL, 2048);
    // hidden 0, 1
    gemm_f16x3<<<gX, 512, SM_TOTAL>>>(O[0], ACTPL, O[0], ACTPL, 2048, 2048, 2048, 2048,
                                      WH0, 4194304ull, 2048,
                                      bh + 0 * X_DIM, mo_h + 0 * X_DIM, aid_h + 0 * X_DIM,
                                      O[1], ACTPL, 2048);
    gemm_f16x3<<<gX, 512, SM_TOTAL>>>(O[1], ACTPL, O[1], ACTPL, 2048, 2048, 2048, 2048,
                                      WH1, 4194304ull, 2048,
                                      bh + 1 * X_DIM, mo_h + 1 * X_DIM, aid_h + 1 * X_DIM,
                                      O[2], ACTPL, 2048);
    // hidden 2: t = concat(outs[2], outs[1])
    gemm_f16x3<<<gX, 512, SM_TOTAL>>>(O[2], ACTPL, O[1], ACTPL, 2048, 2048, 2048, 4096,
                                      WH2, 8388608ull, 4096,
                                      bh + 2 * X_DIM, mo_h + 2 * X_DIM, aid_h + 2 * X_DIM,
                                      O[3], ACTPL, 2048);
    gemm_f16x3<<<gX, 512, SM_TOTAL>>>(O[3], ACTPL, O[3], ACTPL, 2048, 2048, 2048, 2048,
                                      WH3, 4194304ull, 2048,
                                      bh + 3 * X_DIM, mo_h + 3 * X_DIM, aid_h + 3 * X_DIM,
                                      O[4], ACTPL, 2048);
    // hidden 4: t = concat(outs[4], outs[3])
    gemm_f16x3<<<gX, 512, SM_TOTAL>>>(O[4], ACTPL, O[3], ACTPL, 2048, 2048, 2048, 4096,
                                      WH4, 8388608ull, 4096,
                                      bh + 4 * X_DIM, mo_h + 4 * X_DIM, aid_h + 4 * X_DIM,
                                      O[5], ACTPL, 2048);
    gemm_f16x3<<<gX, 512, SM_TOTAL>>>(O[5], ACTPL, O[5], ACTPL, 2048, 2048, 2048, 2048,
                                      WH5, 4194304ull, 2048,
                                      bh + 5 * X_DIM, mo_h + 5 * X_DIM, aid_h + 5 * X_DIM,
                                      O[6], ACTPL, 2048);
    // output layer -> fp32 d_out
    gemm_f16x3<<<gO, 512, SM_TOTAL>>>(O[6], ACTPL, O[6], ACTPL, 2048, 2048, 2048, 2048,
                                      WOUT, 1048576ull, 2048,
                                      b_out, mo_out, aid_out, out, 0ull, 512);
}

// round 16
// speedup vs baseline: 2.4088x; 1.0598x over previous
#include <cuda_runtime.h>
#include <cuda_fp16.h>
#include <cstdint>
#include <math.h>

// ---------------- problem dims ----------------
#define X_DIM 2048

// ---------------- scratch (static device mem; no allocs) ----------------
// All offsets in __half units. Each tensor has 2 fp16 planes (h, l = v - h).
#define ACTPL  8388608ull                  // activation plane [4096,2048]
#define ACT2   (2ull * ACTPL)
#define XB_OFF   117440512ull              // x: plane 4194304, 2 planes
#define WIN_OFF  125829120ull              // plane 2097152
#define WH0_OFF  130023424ull              // plane 4194304
#define WH1_OFF  138412032ull
#define WH2_OFF  146800640ull              // plane 8388608
#define WH3_OFF  163577856ull
#define WH4_OFF  171966464ull              // plane 8388608
#define WH5_OFF  188743680ull
#define WOUT_OFF 197132288ull              // plane 1048576
#define TOTAL_HALVES 199229440ull
__device__ __half g_h[TOTAL_HALVES];

// ---------------- PTX helpers ----------------
__device__ __forceinline__ uint32_t smem_u32(const void* p) {
    uint32_t a;
    asm("{ .reg .u64 t; cvta.to.shared.u64 t, %1; cvt.u32.u64 %0, t; }" : "=r"(a) : "l"(p));
    return a;
}
#define CP_ASYNC16(dst, src) \
    asm volatile("cp.async.cg.shared.global [%0], [%1], 16;" :: "r"(dst), "l"(src) : "memory")
#define CP_COMMIT() asm volatile("cp.async.commit_group;" ::: "memory")
#define CP_WAIT(n)  asm volatile("cp.async.wait_group %0;" :: "n"(n) : "memory")

#define LDSM_X4(r0, r1, r2, r3, addr) \
    asm volatile("ldmatrix.sync.aligned.m8n8.x4.shared.b16 {%0,%1,%2,%3}, [%4];" \
                 : "=r"(r0), "=r"(r1), "=r"(r2), "=r"(r3) : "r"(addr))

// d += a*b (accumulate through TC)
#define MMA_F16(d, a0, a1, a2, a3, b0, b1) \
    asm volatile("mma.sync.aligned.m16n8k16.row.col.f32.f16.f16.f32 " \
                 "{%0,%1,%2,%3}, {%4,%5,%6,%7}, {%8,%9}, {%0,%1,%2,%3};" \
                 : "+f"((d)[0]), "+f"((d)[1]), "+f"((d)[2]), "+f"((d)[3]) \
                 : "r"(a0), "r"(a1), "r"(a2), "r"(a3), "r"(b0), "r"(b1))

// d = a*b (fresh zero accumulator — keeps TC accumulation chains short)
#define MMA_F16_Z(d, a0, a1, a2, a3, b0, b1) \
    asm volatile("mma.sync.aligned.m16n8k16.row.col.f32.f16.f16.f32 " \
                 "{%0,%1,%2,%3}, {%4,%5,%6,%7}, {%8,%9}, {%10,%11,%12,%13};" \
                 : "=f"((d)[0]), "=f"((d)[1]), "=f"((d)[2]), "=f"((d)[3]) \
                 : "r"(a0), "r"(a1), "r"(a2), "r"(a3), "r"(b0), "r"(b1), \
                   "f"(0.0f), "f"(0.0f), "f"(0.0f), "f"(0.0f))

__device__ __forceinline__ uint32_t swz(uint32_t off) { return off ^ ((off >> 3) & 0x70); }

__device__ __forceinline__ void split2(float v, __half& h, __half& l) {
    h = __float2half_rn(v);
    l = __float2half_rn(v - __half2float(h));
}

// ---------------- prologue kernels ----------------
__global__ void split_copy2(const float* __restrict__ in, __half* __restrict__ o,
                            size_t plane, int n) {
    int i = blockIdx.x * blockDim.x + threadIdx.x;
    if (i < n) {
        __half h, l; split2(in[i], h, l);
        o[i] = h; o[i + plane] = l;
    }
}

// in [R,C] fp32 row-major -> out [C,R] fp16 row-major, 2 planes
__global__ void transpose_split2(const float* __restrict__ in, __half* __restrict__ o,
                                 size_t plane, int R, int C) {
    __shared__ float t[32][33];
    int cx = blockIdx.x * 32 + threadIdx.x;
    int r0 = blockIdx.y * 32;
#pragma unroll
    for (int j = threadIdx.y; j < 32; j += 8)
        t[j][threadIdx.x] = in[(size_t)(r0 + j) * C + cx];
    __syncthreads();
    int rx = r0 + threadIdx.x;
    int c0 = blockIdx.x * 32;
#pragma unroll
    for (int j = threadIdx.y; j < 32; j += 8) {
        __half h, l; split2(t[threadIdx.x][j], h, l);
        size_t idx = (size_t)(c0 + j) * R + rx;
        o[idx] = h; o[idx + plane] = l;
    }
}

// ---------------- epilogue activation ----------------
__device__ __forceinline__ float epi(float v, float b, int a, float m) {
    v += b;
    float r;
    if (a == 0)      r = fmaxf(v, 0.0f);
    else if (a == 1) r = 1.0f / (1.0f + expf(-v));
    else if (a == 2) r = tanhf(v);
    else if (a == 3) r = (v >= 0.0f) ? v : 0.1f * v;
    else             r = (v > 0.0f) ? 1.0507009873554805f * v
                                    : 1.7580993408473766f * expm1f(v);
    return fminf(r, m);
}

// ---------------- fp16 2-split / 3-MMA GEMM, external fp32 accumulation ----------------
// C[4096, Ntot] = act( [A1 | A2] @ Wt^T + bias ).
// CTA tile 64(M) x 128(N) x 64(K halves); 256 threads, 8 warps as 2(M) x 4(N),
// warp tile 32x32. 2-stage cp.async pipeline, ONE barrier per chunk,
// 2 CTAs per SM (96KB smem, <=128 regs).
// Per k16 step: t = ah*bh + ah*bl + al*bh in a short TC chain from zero,
// then folded into register fp32 sums (RN).
#define STAGE_BYTES 49152           // Ah 8K + Al 8K + Bh 16K + Bl 16K
#define SM_TOTAL (2 * STAGE_BYTES)

__global__ __launch_bounds__(256, 2)
void gemm_f16x3(const __half* __restrict__ A1, size_t pA1,
                const __half* __restrict__ A2, size_t pA2,
                int lda1, int lda2, int K1, int Ktot,
                const __half* __restrict__ W, size_t pW, int ldw,
                const float* __restrict__ bias, const float* __restrict__ mo,
                const int* __restrict__ aid,
                void* __restrict__ Cout, size_t pC, int Ntot) {
    extern __shared__ char smem[];
    const uint32_t sb = smem_u32(smem);
    const int tid = threadIdx.x;
    const int block_m = blockIdx.y * 64;
    const int block_n = blockIdx.x * 128;

    // 8 warps as 2 (M) x 4 (N); warp tile 32x32
    const int warp = tid >> 5;
    const int lane = tid & 31;
    const int wm = warp >> 2;           // 0..1 -> m offset wm*32
    const int wn = warp & 3;            // 0..3 -> n offset wn*32
    const int g   = lane >> 2;
    const int tig = lane & 3;

    const int lrow = (lane & 7) + ((lane >> 3) & 1) * 8;
    const int lcol = ((lane >> 4) & 1) * 16;

    // loader geometry:
    // A plane (64 rows x 128B): row = tid>>2, 2 granules at (tid&3)*2 + i
    // B plane (128 rows x 128B): row = tid>>1, 4 granules at (tid&1)*4 + i
    const int arow = tid >> 2;
    const int aq0  = (tid & 3) * 2;
    const int brow = tid >> 1;
    const int bq0  = (tid & 1) * 4;
    uint32_t dstoA[2], dstoB[4];
#pragma unroll
    for (int i = 0; i < 2; i++) dstoA[i] = swz((uint32_t)(arow * 128 + (aq0 + i) * 16));
#pragma unroll
    for (int i = 0; i < 4; i++) dstoB[i] = swz((uint32_t)(brow * 128 + (bq0 + i) * 16));

    const __half* a1p = A1 + (size_t)(block_m + arow) * lda1 + aq0 * 8;
    const __half* a2p = A2 + (size_t)(block_m + arow) * lda2 + aq0 * 8;
    const __half* bp  = W  + (size_t)(block_n + brow) * ldw  + bq0 * 8;

    float sum[2][4][4];
#pragma unroll
    for (int i = 0; i < 2; i++)
#pragma unroll
        for (int j = 0; j < 4; j++)
#pragma unroll
            for (int c = 0; c < 4; c++) sum[i][j][c] = 0.0f;

    const int NC = Ktot / 64;

    auto load_stage = [&](int c, int s) {
        const uint32_t st = sb + s * STAGE_BYTES;
        const int k0 = c * 64;
        const __half* ap; size_t pa;
        if (k0 < K1) { ap = a1p + k0;        pa = pA1; }
        else         { ap = a2p + (k0 - K1); pa = pA2; }
#pragma unroll
        for (int p = 0; p < 2; p++) {
            const __half* src = ap + (size_t)p * pa;
#pragma unroll
            for (int i = 0; i < 2; i++) CP_ASYNC16(st + p * 8192 + dstoA[i], src + i * 8);
        }
        const __half* wp = bp + k0;
#pragma unroll
        for (int p = 0; p < 2; p++) {
            const __half* src = wp + (size_t)p * pW;
#pragma unroll
            for (int i = 0; i < 4; i++) CP_ASYNC16(st + 16384 + p * 16384 + dstoB[i], src + i * 8);
        }
        CP_COMMIT();
    };

    load_stage(0, 0);

    for (int c = 0; c < NC; c++) {
        const int s = c & 1;
        CP_WAIT(0);             // chunk c landed (committed one iteration ago)
        __syncthreads();        // publish chunk c; fence compute(c-1) vs prefetch below
        if (c + 1 < NC) load_stage(c + 1, s ^ 1);

        const uint32_t Ahb = sb + s * STAGE_BYTES;
        const uint32_t Alb = Ahb + 8192;
        const uint32_t Bhb = Ahb + 16384;
        const uint32_t Blb = Ahb + 32768;

#pragma unroll
        for (int k = 0; k < 4; k++) {       // 4 x k16 steps
            uint32_t bh[2][4], bl[2][4];
#pragma unroll
            for (int nj = 0; nj < 2; nj++) {
                uint32_t off = swz((uint32_t)((wn * 32 + nj * 16 + lrow) * 128 + k * 32 + lcol));
                LDSM_X4(bh[nj][0], bh[nj][1], bh[nj][2], bh[nj][3], Bhb + off);
                LDSM_X4(bl[nj][0], bl[nj][1], bl[nj][2], bl[nj][3], Blb + off);
            }
#pragma unroll
            for (int mi = 0; mi < 2; mi++) {
                uint32_t off = swz((uint32_t)((wm * 32 + mi * 16 + lrow) * 128 + k * 32 + lcol));
                uint32_t ah0, ah1, ah2, ah3, al0, al1, al2, al3;
                LDSM_X4(ah0, ah1, ah2, ah3, Ahb + off);
                LDSM_X4(al0, al1, al2, al3, Alb + off);
#pragma unroll
                for (int ni = 0; ni < 4; ni++) {
                    const int nj = ni >> 1, p = ni & 1;
                    float t[4];
                    // short TC chain from zero: hh + hl + lh
                    MMA_F16_Z(t, ah0, ah1, ah2, ah3, bh[nj][p], bh[nj][p + 2]);
                    MMA_F16 (t, ah0, ah1, ah2, ah3, bl[nj][p], bl[nj][p + 2]);
                    MMA_F16 (t, al0, al1, al2, al3, bh[nj][p], bh[nj][p + 2]);
                    sum[mi][ni][0] += t[0]; sum[mi][ni][1] += t[1];
                    sum[mi][ni][2] += t[2]; sum[mi][ni][3] += t[3];
                }
            }
        }
    }

    // fused epilogue
    float bv[4][2], mv[4][2]; int av[4][2];
#pragma unroll
    for (int ni = 0; ni < 4; ni++) {
        int cc = block_n + wn * 32 + ni * 8 + 2 * tig;
        bv[ni][0] = bias[cc];     bv[ni][1] = bias[cc + 1];
        mv[ni][0] = mo[cc];       mv[ni][1] = mo[cc + 1];
        av[ni][0] = aid[cc];      av[ni][1] = aid[cc + 1];
    }
    if (pC != 0) {
        __half* Ch = (__half*)Cout;
#pragma unroll
        for (int mi = 0; mi < 2; mi++) {
            const int r0 = block_m + wm * 32 + mi * 16 + g;
#pragma unroll
            for (int ni = 0; ni < 4; ni++) {
                const int cc = block_n + wn * 32 + ni * 8 + 2 * tig;
#pragma unroll
                for (int hrow = 0; hrow < 2; hrow++) {
                    const size_t idx = (size_t)(r0 + hrow * 8) * Ntot + cc;
                    float v0 = epi(sum[mi][ni][2*hrow+0], bv[ni][0], av[ni][0], mv[ni][0]);
                    float v1 = epi(sum[mi][ni][2*hrow+1], bv[ni][1], av[ni][1], mv[ni][1]);
                    __half h0, l0, h1, l1;
                    split2(v0, h0, l0);
                    split2(v1, h1, l1);
                    *reinterpret_cast<__half2*>(Ch + idx)      = __halves2half2(h0, h1);
                    *reinterpret_cast<__half2*>(Ch + idx + pC) = __halves2half2(l0, l1);
                }
            }
        }
    } else {
        float* Cf = (float*)Cout;
#pragma unroll
        for (int mi = 0; mi < 2; mi++) {
            const int r0 = block_m + wm * 32 + mi * 16 + g;
#pragma unroll
            for (int ni = 0; ni < 4; ni++) {
                const int cc = block_n + wn * 32 + ni * 8 + 2 * tig;
#pragma unroll
                for (int hrow = 0; hrow < 2; hrow++) {
                    float2 v;
                    v.x = epi(sum[mi][ni][2*hrow+0], bv[ni][0], av[ni][0], mv[ni][0]);
                    v.y = epi(sum[mi][ni][2*hrow+1], bv[ni][1], av[ni][1], mv[ni][1]);
                    *reinterpret_cast<float2*>(Cf + (size_t)(r0 + hrow * 8) * Ntot + cc) = v;
                }
            }
        }
    }
}

// ---------------- host ----------------
extern "C" void kernel_launch(void* const* d_in, const int* in_sizes, int n_in,
                              void* d_out, int out_size) {
    const float* x     = (const float*)d_in[0];
    const float* W_in  = (const float*)d_in[1];
    const float* b_in  = (const float*)d_in[2];
    const float* Wh[6] = { (const float*)d_in[3], (const float*)d_in[4], (const float*)d_in[5],
                           (const float*)d_in[6], (const float*)d_in[7], (const float*)d_in[8] };
    const float* bh     = (const float*)d_in[9];
    const float* W_out  = (const float*)d_in[10];
    const float* b_out  = (const float*)d_in[11];
    const float* mo_in  = (const float*)d_in[12];
    const float* mo_h   = (const float*)d_in[13];
    const float* mo_out = (const float*)d_in[14];
    const int* aid_in   = (const int*)d_in[15];
    const int* aid_h    = (const int*)d_in[16];
    const int* aid_out  = (const int*)d_in[17];
    float* out = (float*)d_out;

    __half* s = nullptr;
    cudaGetSymbolAddress((void**)&s, g_h);

    cudaFuncSetAttribute(gemm_f16x3, cudaFuncAttributeMaxDynamicSharedMemorySize, SM_TOTAL);

    __half* O[7];
    for (int i = 0; i < 7; i++) O[i] = s + (size_t)i * ACT2;
    __half* XB   = s + XB_OFF;
    __half* WIN  = s + WIN_OFF;
    __half* WH0  = s + WH0_OFF;
    __half* WH1  = s + WH1_OFF;
    __half* WH2  = s + WH2_OFF;
    __half* WH3  = s + WH3_OFF;
    __half* WH4  = s + WH4_OFF;
    __half* WH5  = s + WH5_OFF;
    __half* WOUT = s + WOUT_OFF;

    dim3 tb(32, 8);
    split_copy2<<<16384, 256>>>(x, XB, 4194304ull, 4096 * 1024);
    transpose_split2<<<dim3(64, 32),  tb>>>(W_in,  WIN,  2097152ull, 1024, 2048);
    transpose_split2<<<dim3(64, 64),  tb>>>(Wh[0], WH0,  4194304ull, 2048, 2048);
    transpose_split2<<<dim3(64, 64),  tb>>>(Wh[1], WH1,  4194304ull, 2048, 2048);
    transpose_split2<<<dim3(64, 128), tb>>>(Wh[2], WH2,  8388608ull, 4096, 2048);
    transpose_split2<<<dim3(64, 64),  tb>>>(Wh[3], WH3,  4194304ull, 2048, 2048);
    transpose_split2<<<dim3(64, 128), tb>>>(Wh[4], WH4,  8388608ull, 4096, 2048);
    transpose_split2<<<dim3(64, 64),  tb>>>(Wh[5], WH5,  4194304ull, 2048, 2048);
    transpose_split2<<<dim3(16, 64),  tb>>>(W_out, WOUT, 1048576ull, 2048, 512);

    dim3 gX(16, 64), gO(4, 64);
    // input layer
    gemm_f16x3<<<gX, 256, SM_TOTAL>>>(XB, 4194304ull, XB, 4194304ull, 1024, 1024, 1024, 1024,
                                      WIN, 2097152ull, 1024,
                                      b_in, mo_in, aid_in, O[0], ACTPL, 2048);
    // hidden 0, 1
    gemm_f16x3<<<gX, 256, SM_TOTAL>>>(O[0], ACTPL, O[0], ACTPL, 2048, 2048, 2048, 2048,
                                      WH0, 4194304ull, 2048,
                                      bh + 0 * X_DIM, mo_h + 0 * X_DIM, aid_h + 0 * X_DIM,
                                      O[1], ACTPL, 2048);
    gemm_f16x3<<<gX, 256, SM_TOTAL>>>(O[1], ACTPL, O[1], ACTPL, 2048, 2048, 2048, 2048,
                                      WH1, 4194304ull, 2048,
                                      bh + 1 * X_DIM, mo_h + 1 * X_DIM, aid_h + 1 * X_DIM,
                                      O[2], ACTPL, 2048);
    // hidden 2: t = concat(outs[2], outs[1])
    gemm_f16x3<<<gX, 256, SM_TOTAL>>>(O[2], ACTPL, O[1], ACTPL, 2048, 2048, 2048, 4096,
                                      WH2, 8388608ull, 4096,
                                      bh + 2 * X_DIM, mo_h + 2 * X_DIM, aid_h + 2 * X_DIM,
                                      O[3], ACTPL, 2048);
    gemm_f16x3<<<gX, 256, SM_TOTAL>>>(O[3], ACTPL, O[3], ACTPL, 2048, 2048, 2048, 2048,
                                      WH3, 4194304ull, 2048,
                                      bh + 3 * X_DIM, mo_h + 3 * X_DIM, aid_h + 3 * X_DIM,
                                      O[4], ACTPL, 2048);
    // hidden 4: t = concat(outs[4], outs[3])
    gemm_f16x3<<<gX, 256, SM_TOTAL>>>(O[4], ACTPL, O[3], ACTPL, 2048, 2048, 2048, 4096,
                                      WH4, 8388608ull, 4096,
                                      bh + 4 * X_DIM, mo_h + 4 * X_DIM, aid_h + 4 * X_DIM,
                                      O[5], ACTPL, 2048);
    gemm_f16x3<<<gX, 256, SM_TOTAL>>>(O[5], ACTPL, O[5], ACTPL, 2048, 2048, 2048, 2048,
                                      WH5, 4194304ull, 2048,
                                      bh + 5 * X_DIM, mo_h + 5 * X_DIM, aid_h + 5 * X_DIM,
                                      O[6], ACTPL, 2048);
    // output layer -> fp32 d_out
    gemm_f16x3<<<gO, 256, SM_TOTAL>>>(O[6], ACTPL, O[6], ACTPL, 2048, 2048, 2048, 2048,
                                      WOUT, 1048576ull, 2048,
                                      b_out, mo_out, aid_out, out, 0ull, 512);
}